// round 2
// baseline (speedup 1.0000x reference)
#include <cuda_runtime.h>
#include <cuda_bf16.h>

typedef unsigned long long ull;

#define RT   32      // batch rows per CTA
#define NT   256     // threads per CTA
#define SSTR 80      // stride (floats) of state arrays [RT x 64]
#define HSTR 260     // stride (floats) of hidden [RT x 256]
#define Dd   64
#define Hh   256
#define Oo   32

struct SMEM {
    float W1 [Dd * Hh];    // [d][h] row-major
    float W2 [Hh * Dd];    // [h][d] row-major
    float Wfc[Dd * Oo];    // [d][o] row-major
    float b1 [Hh];
    float b2 [Dd];
    float bfc[Oo];
    float tv [64];
    float Y  [RT * SSTR];
    float YT [RT * SSTR];
    float ACC[RT * SSTR];
    float F0 [RT * SSTR];
    float F1 [RT * SSTR];
    float HID[RT * HSTR];
};
// sizeof(SMEM) = 225408 bytes <= 232448 (sm_103a dynamic smem limit)

// ---------------- packed fp32x2 helpers ----------------
__device__ __forceinline__ void fma2(ull& d, ull a, ull b) {
#if __CUDA_ARCH__ >= 1000
    asm("fma.rn.f32x2 %0, %1, %2, %0;" : "+l"(d) : "l"(a), "l"(b));
#else
    float2& dd = reinterpret_cast<float2&>(d);
    const float2& aa = reinterpret_cast<const float2&>(a);
    const float2& bb = reinterpret_cast<const float2&>(b);
    dd.x = fmaf(aa.x, bb.x, dd.x);
    dd.y = fmaf(aa.y, bb.y, dd.y);
#endif
}
__device__ __forceinline__ ull pk(float x, float y) {
    ull r;
    asm("mov.b64 %0, {%1, %2};" : "=l"(r) : "f"(x), "f"(y));
    return r;
}
__device__ __forceinline__ ull bc2(float x) { return pk(x, x); }
__device__ __forceinline__ float2 upk(ull v) {
    float2 r;
    asm("mov.b64 {%0, %1}, %2;" : "=f"(r.x), "=f"(r.y) : "l"(v));
    return r;
}

// accurate tanh: 2 MUFU (ex2 + rcp), abs err ~1e-6
__device__ __forceinline__ float tanh_acc(float x) {
    const float NL2E2 = -2.885390081777927f;   // -2*log2(e)
    float ax = fabsf(x);
    float e, r;
    asm("ex2.approx.f32 %0, %1;" : "=f"(e) : "f"(NL2E2 * ax)); // exp(-2|x|)
    asm("rcp.approx.f32 %0, %1;" : "=f"(r) : "f"(1.0f + e));
    float t = (1.0f - e) * r;
    return copysignf(t, x);
}

__device__ __forceinline__ float getc(float4 v, int k) {
    switch (k) { case 0: return v.x; case 1: return v.y; case 2: return v.z; default: return v.w; }
}

// ---------------- GEMM1 + tanh -> HID ----------------
// thread (ty in [0,4), tx in [0,64)): rows ty*8..+8, cols {2tx, 2tx+1} and {2tx+128, 2tx+129}
__device__ __forceinline__ void gemm1_tanh(SMEM& s, const float* __restrict__ SRC, int tid) {
    const int tx = tid & 63;
    const int ty = tid >> 6;
    const int r0 = ty * 8;
    const int c0 = 2 * tx;
    const int c1 = c0 + 128;

    ull a0[8], a1[8];
    {
        float2 bi0 = *(const float2*)&s.b1[c0];
        float2 bi1 = *(const float2*)&s.b1[c1];
        ull p0 = pk(bi0.x, bi0.y), p1 = pk(bi1.x, bi1.y);
#pragma unroll
        for (int i = 0; i < 8; i++) { a0[i] = p0; a1[i] = p1; }
    }

#pragma unroll 2
    for (int d0 = 0; d0 < Dd; d0 += 4) {
        float4 yv[8];
#pragma unroll
        for (int i = 0; i < 8; i++)
            yv[i] = *(const float4*)&SRC[(r0 + i) * SSTR + d0];
#pragma unroll
        for (int dd = 0; dd < 4; dd++) {
            ull w0 = *(const ull*)&s.W1[(d0 + dd) * Hh + c0];
            ull w1 = *(const ull*)&s.W1[(d0 + dd) * Hh + c1];
#pragma unroll
            for (int i = 0; i < 8; i++) {
                ull ys = bc2(getc(yv[i], dd));
                fma2(a0[i], ys, w0);
                fma2(a1[i], ys, w1);
            }
        }
    }

#pragma unroll
    for (int i = 0; i < 8; i++) {
        float2 v0 = upk(a0[i]);
        float2 v1 = upk(a1[i]);
        v0.x = tanh_acc(v0.x); v0.y = tanh_acc(v0.y);
        v1.x = tanh_acc(v1.x); v1.y = tanh_acc(v1.y);
        *(float2*)&s.HID[(r0 + i) * HSTR + c0] = v0;
        *(float2*)&s.HID[(r0 + i) * HSTR + c1] = v1;
    }
}

// ---------------- GEMM2 -> F0/F1 (2-way h-split partials) ----------------
// g = tid>>7 handles h in [g*128, g*128+128); thread: rows ty2*8..+8, cols {2tx2, 2tx2+1}
__device__ __forceinline__ void gemm2(SMEM& s, int tid) {
    const int g   = tid >> 7;
    const int t2  = tid & 127;
    const int ty2 = t2 >> 5;
    const int tx2 = t2 & 31;
    const int r0  = ty2 * 8;
    const int dc  = 2 * tx2;
    const int hb  = g * 128;

    ull b[8];
    {
        ull init = 0;
        if (g == 0) {
            float2 bb = *(const float2*)&s.b2[dc];
            init = pk(bb.x, bb.y);
        }
#pragma unroll
        for (int i = 0; i < 8; i++) b[i] = init;
    }

#pragma unroll 2
    for (int h0 = 0; h0 < 128; h0 += 4) {
        float4 hv[8];
#pragma unroll
        for (int i = 0; i < 8; i++)
            hv[i] = *(const float4*)&s.HID[(r0 + i) * HSTR + hb + h0];
#pragma unroll
        for (int hh = 0; hh < 4; hh++) {
            ull w = *(const ull*)&s.W2[(hb + h0 + hh) * Dd + dc];
#pragma unroll
            for (int i = 0; i < 8; i++)
                fma2(b[i], bc2(getc(hv[i], hh)), w);
        }
    }

    float* F = g ? s.F1 : s.F0;
#pragma unroll
    for (int i = 0; i < 8; i++)
        *(float2*)&F[(r0 + i) * SSTR + dc] = upk(b[i]);
}

// ---------------- elementwise RK4 stage updates ----------------
// each thread owns 8 floats: row = tid>>3, cols (tid&7)*8 .. +8
template <int ST>
__device__ __forceinline__ void rk_update(SMEM& s, int tid, float h) {
    const int r  = tid >> 3;
    const int cb = (tid & 7) * 8;
    const int o  = r * SSTR + cb;
    const float h2 = 0.5f * h;
    const float h6 = h * (1.0f / 6.0f);

#pragma unroll
    for (int j = 0; j < 2; j++) {
        int oo = o + j * 4;
        float4 f0 = *(const float4*)&s.F0[oo];
        float4 f1 = *(const float4*)&s.F1[oo];
        float4 k;
        k.x = f0.x + f1.x; k.y = f0.y + f1.y; k.z = f0.z + f1.z; k.w = f0.w + f1.w;

        if (ST == 0) {
            float4 y = *(const float4*)&s.Y[oo];
            *(float4*)&s.ACC[oo] = k;
            float4 yt;
            yt.x = fmaf(h2, k.x, y.x); yt.y = fmaf(h2, k.y, y.y);
            yt.z = fmaf(h2, k.z, y.z); yt.w = fmaf(h2, k.w, y.w);
            *(float4*)&s.YT[oo] = yt;
        } else if (ST == 1 || ST == 2) {
            float4 y = *(const float4*)&s.Y[oo];
            float4 a = *(const float4*)&s.ACC[oo];
            a.x = fmaf(2.0f, k.x, a.x); a.y = fmaf(2.0f, k.y, a.y);
            a.z = fmaf(2.0f, k.z, a.z); a.w = fmaf(2.0f, k.w, a.w);
            *(float4*)&s.ACC[oo] = a;
            const float hs = (ST == 1) ? h2 : h;
            float4 yt;
            yt.x = fmaf(hs, k.x, y.x); yt.y = fmaf(hs, k.y, y.y);
            yt.z = fmaf(hs, k.z, y.z); yt.w = fmaf(hs, k.w, y.w);
            *(float4*)&s.YT[oo] = yt;
        } else {
            float4 y = *(const float4*)&s.Y[oo];
            float4 a = *(const float4*)&s.ACC[oo];
            a.x += k.x; a.y += k.y; a.z += k.z; a.w += k.w;
            y.x = fmaf(h6, a.x, y.x); y.y = fmaf(h6, a.y, y.y);
            y.z = fmaf(h6, a.z, y.z); y.w = fmaf(h6, a.w, y.w);
            *(float4*)&s.Y[oo] = y;
        }
    }
}

// ---------------- one f-eval: SRC -> F0,F1 ----------------
__device__ __forceinline__ void feval(SMEM& s, const float* __restrict__ SRC, int tid) {
    gemm1_tanh(s, SRC, tid);
    __syncthreads();
    gemm2(s, tid);
    __syncthreads();
}

// ---------------- projection: out[sp] = Y @ Wfc + bfc ----------------
__device__ __forceinline__ void project(SMEM& s, float* __restrict__ out,
                                        int sp, int base, int B, int tid) {
    const int r  = tid >> 3;           // 0..31
    const int og = (tid & 7) * 4;      // 0..28
    float4 acc = *(const float4*)&s.bfc[og];
#pragma unroll 4
    for (int d = 0; d < Dd; d++) {
        float y = s.Y[r * SSTR + d];
        float4 w = *(const float4*)&s.Wfc[d * Oo + og];
        acc.x = fmaf(y, w.x, acc.x); acc.y = fmaf(y, w.y, acc.y);
        acc.z = fmaf(y, w.z, acc.z); acc.w = fmaf(y, w.w, acc.w);
    }
    size_t off = ((size_t)sp * B + base + r) * Oo + og;
    *(float4*)&out[off] = acc;
}

__global__ void __launch_bounds__(NT, 1)
node_kernel(const float* __restrict__ y0, const float* __restrict__ tarr,
            const float* __restrict__ W1, const float* __restrict__ b1,
            const float* __restrict__ W2, const float* __restrict__ b2,
            const float* __restrict__ Wfc, const float* __restrict__ bfc,
            float* __restrict__ out, int B, int T) {
    extern __shared__ float smem_f[];
    SMEM& s = *reinterpret_cast<SMEM*>(smem_f);
    const int tid  = threadIdx.x;
    const int base = blockIdx.x * RT;

    // ---- load weights / biases / t / y0 tile into SMEM ----
    for (int i = tid; i < Dd * Hh / 4; i += NT)
        ((float4*)s.W1)[i] = ((const float4*)W1)[i];
    for (int i = tid; i < Hh * Dd / 4; i += NT)
        ((float4*)s.W2)[i] = ((const float4*)W2)[i];
    for (int i = tid; i < Dd * Oo / 4; i += NT)
        ((float4*)s.Wfc)[i] = ((const float4*)Wfc)[i];
    for (int i = tid; i < Hh / 4; i += NT)
        ((float4*)s.b1)[i] = ((const float4*)b1)[i];
    if (tid < Dd / 4) ((float4*)s.b2)[tid] = ((const float4*)b2)[tid];
    if (tid < Oo / 4) ((float4*)s.bfc)[tid] = ((const float4*)bfc)[tid];
    if (tid < T && tid < 64) s.tv[tid] = tarr[tid];
    for (int i = tid; i < RT * Dd / 4; i += NT) {
        int r = i >> 4, d4 = i & 15;
        ((float4*)&s.Y[r * SSTR])[d4] = ((const float4*)&y0[(size_t)(base + r) * Dd])[d4];
    }
    __syncthreads();

    // ---- time integration ----
    for (int sp = 0; sp < T; sp++) {
        project(s, out, sp, base, B, tid);
        if (sp == T - 1) break;
        float dt = s.tv[sp + 1] - s.tv[sp];
        float h  = dt * 0.125f;    // dt / N_SUB

        for (int sub = 0; sub < 8; sub++) {
            feval(s, s.Y, tid);
            rk_update<0>(s, tid, h);
            __syncthreads();
            feval(s, s.YT, tid);
            rk_update<1>(s, tid, h);
            __syncthreads();
            feval(s, s.YT, tid);
            rk_update<2>(s, tid, h);
            __syncthreads();
            feval(s, s.YT, tid);
            rk_update<3>(s, tid, h);
            __syncthreads();
        }
    }
}

extern "C" void kernel_launch(void* const* d_in, const int* in_sizes, int n_in,
                              void* d_out, int out_size) {
    const float* y0  = (const float*)d_in[0];
    const float* t   = (const float*)d_in[1];
    const float* W1  = (const float*)d_in[2];
    const float* b1  = (const float*)d_in[3];
    const float* W2  = (const float*)d_in[4];
    const float* b2  = (const float*)d_in[5];
    const float* Wfc = (const float*)d_in[6];
    const float* bfc = (const float*)d_in[7];
    float* out = (float*)d_out;

    int B = in_sizes[0] / Dd;
    int T = in_sizes[1];

    size_t smem = sizeof(SMEM);
    cudaFuncSetAttribute(node_kernel, cudaFuncAttributeMaxDynamicSharedMemorySize, (int)smem);
    node_kernel<<<B / RT, NT, smem>>>(y0, t, W1, b1, W2, b2, Wfc, bfc, out, B, T);
}

// round 3
// speedup vs baseline: 1.0001x; 1.0001x over previous
#include <cuda_runtime.h>
#include <cuda_bf16.h>

typedef unsigned long long ull;

#define RT   32      // batch rows per CTA
#define NT   256     // threads per CTA
#define SSTR 80      // stride (floats) of state arrays [RT x 64]
#define HSTR 260     // stride (floats) of hidden [RT x 256]
#define Dd   64
#define Hh   256
#define Oo   32

struct SMEM {
    float W1 [Dd * Hh];    // [d][h] row-major
    float W2 [Hh * Dd];    // [h][d] row-major
    float Wfc[Dd * Oo];    // [d][o] row-major
    float b1 [Hh];
    float b2 [Dd];
    float bfc[Oo];
    float tv [64];
    float Y  [RT * SSTR];
    float YT [RT * SSTR];
    float ACC[RT * SSTR];
    float F0 [RT * SSTR];
    float F1 [RT * SSTR];
    float HID[RT * HSTR];
};
// sizeof(SMEM) = 225408 bytes <= 232448 (sm_103a dynamic smem limit)

// ---------------- packed fp32x2 helpers ----------------
__device__ __forceinline__ void fma2(ull& d, ull a, ull b) {
#if __CUDA_ARCH__ >= 1000
    asm("fma.rn.f32x2 %0, %1, %2, %0;" : "+l"(d) : "l"(a), "l"(b));
#else
    float2& dd = reinterpret_cast<float2&>(d);
    const float2& aa = reinterpret_cast<const float2&>(a);
    const float2& bb = reinterpret_cast<const float2&>(b);
    dd.x = fmaf(aa.x, bb.x, dd.x);
    dd.y = fmaf(aa.y, bb.y, dd.y);
#endif
}
__device__ __forceinline__ ull pk(float x, float y) {
    ull r;
    asm("mov.b64 %0, {%1, %2};" : "=l"(r) : "f"(x), "f"(y));
    return r;
}
__device__ __forceinline__ ull bc2(float x) { return pk(x, x); }
__device__ __forceinline__ float2 upk(ull v) {
    float2 r;
    asm("mov.b64 {%0, %1}, %2;" : "=f"(r.x), "=f"(r.y) : "l"(v));
    return r;
}

// accurate tanh: 2 MUFU (ex2 + rcp), abs err ~1e-6
__device__ __forceinline__ float tanh_acc(float x) {
    const float NL2E2 = -2.885390081777927f;   // -2*log2(e)
    float ax = fabsf(x);
    float e, r;
    asm("ex2.approx.f32 %0, %1;" : "=f"(e) : "f"(NL2E2 * ax)); // exp(-2|x|)
    asm("rcp.approx.f32 %0, %1;" : "=f"(r) : "f"(1.0f + e));
    float t = (1.0f - e) * r;
    return copysignf(t, x);
}

__device__ __forceinline__ float getc(float4 v, int k) {
    switch (k) { case 0: return v.x; case 1: return v.y; case 2: return v.z; default: return v.w; }
}

// ---------------- GEMM1 + tanh -> HID ----------------
// thread (ty in [0,4), tx in [0,64)): rows ty*8..+8, cols {2tx, 2tx+1} and {2tx+128, 2tx+129}
__device__ __forceinline__ void gemm1_tanh(SMEM& s, const float* __restrict__ SRC, int tid) {
    const int tx = tid & 63;
    const int ty = tid >> 6;
    const int r0 = ty * 8;
    const int c0 = 2 * tx;
    const int c1 = c0 + 128;

    ull a0[8], a1[8];
    {
        float2 bi0 = *(const float2*)&s.b1[c0];
        float2 bi1 = *(const float2*)&s.b1[c1];
        ull p0 = pk(bi0.x, bi0.y), p1 = pk(bi1.x, bi1.y);
#pragma unroll
        for (int i = 0; i < 8; i++) { a0[i] = p0; a1[i] = p1; }
    }

#pragma unroll 2
    for (int d0 = 0; d0 < Dd; d0 += 4) {
        float4 yv[8];
#pragma unroll
        for (int i = 0; i < 8; i++)
            yv[i] = *(const float4*)&SRC[(r0 + i) * SSTR + d0];
#pragma unroll
        for (int dd = 0; dd < 4; dd++) {
            ull w0 = *(const ull*)&s.W1[(d0 + dd) * Hh + c0];
            ull w1 = *(const ull*)&s.W1[(d0 + dd) * Hh + c1];
#pragma unroll
            for (int i = 0; i < 8; i++) {
                ull ys = bc2(getc(yv[i], dd));
                fma2(a0[i], ys, w0);
                fma2(a1[i], ys, w1);
            }
        }
    }

#pragma unroll
    for (int i = 0; i < 8; i++) {
        float2 v0 = upk(a0[i]);
        float2 v1 = upk(a1[i]);
        v0.x = tanh_acc(v0.x); v0.y = tanh_acc(v0.y);
        v1.x = tanh_acc(v1.x); v1.y = tanh_acc(v1.y);
        *(float2*)&s.HID[(r0 + i) * HSTR + c0] = v0;
        *(float2*)&s.HID[(r0 + i) * HSTR + c1] = v1;
    }
}

// ---------------- GEMM2 -> F0/F1 (2-way h-split partials) ----------------
// g = tid>>7 handles h in [g*128, g*128+128); thread: rows ty2*8..+8, cols {2tx2, 2tx2+1}
__device__ __forceinline__ void gemm2(SMEM& s, int tid) {
    const int g   = tid >> 7;
    const int t2  = tid & 127;
    const int ty2 = t2 >> 5;
    const int tx2 = t2 & 31;
    const int r0  = ty2 * 8;
    const int dc  = 2 * tx2;
    const int hb  = g * 128;

    ull b[8];
    {
        ull init = 0;
        if (g == 0) {
            float2 bb = *(const float2*)&s.b2[dc];
            init = pk(bb.x, bb.y);
        }
#pragma unroll
        for (int i = 0; i < 8; i++) b[i] = init;
    }

#pragma unroll 2
    for (int h0 = 0; h0 < 128; h0 += 4) {
        float4 hv[8];
#pragma unroll
        for (int i = 0; i < 8; i++)
            hv[i] = *(const float4*)&s.HID[(r0 + i) * HSTR + hb + h0];
#pragma unroll
        for (int hh = 0; hh < 4; hh++) {
            ull w = *(const ull*)&s.W2[(hb + h0 + hh) * Dd + dc];
#pragma unroll
            for (int i = 0; i < 8; i++)
                fma2(b[i], bc2(getc(hv[i], hh)), w);
        }
    }

    float* F = g ? s.F1 : s.F0;
#pragma unroll
    for (int i = 0; i < 8; i++)
        *(float2*)&F[(r0 + i) * SSTR + dc] = upk(b[i]);
}

// ---------------- elementwise RK4 stage updates ----------------
// each thread owns 8 floats: row = tid>>3, cols (tid&7)*8 .. +8
template <int ST>
__device__ __forceinline__ void rk_update(SMEM& s, int tid, float h) {
    const int r  = tid >> 3;
    const int cb = (tid & 7) * 8;
    const int o  = r * SSTR + cb;
    const float h2 = 0.5f * h;
    const float h6 = h * (1.0f / 6.0f);

#pragma unroll
    for (int j = 0; j < 2; j++) {
        int oo = o + j * 4;
        float4 f0 = *(const float4*)&s.F0[oo];
        float4 f1 = *(const float4*)&s.F1[oo];
        float4 k;
        k.x = f0.x + f1.x; k.y = f0.y + f1.y; k.z = f0.z + f1.z; k.w = f0.w + f1.w;

        if (ST == 0) {
            float4 y = *(const float4*)&s.Y[oo];
            *(float4*)&s.ACC[oo] = k;
            float4 yt;
            yt.x = fmaf(h2, k.x, y.x); yt.y = fmaf(h2, k.y, y.y);
            yt.z = fmaf(h2, k.z, y.z); yt.w = fmaf(h2, k.w, y.w);
            *(float4*)&s.YT[oo] = yt;
        } else if (ST == 1 || ST == 2) {
            float4 y = *(const float4*)&s.Y[oo];
            float4 a = *(const float4*)&s.ACC[oo];
            a.x = fmaf(2.0f, k.x, a.x); a.y = fmaf(2.0f, k.y, a.y);
            a.z = fmaf(2.0f, k.z, a.z); a.w = fmaf(2.0f, k.w, a.w);
            *(float4*)&s.ACC[oo] = a;
            const float hs = (ST == 1) ? h2 : h;
            float4 yt;
            yt.x = fmaf(hs, k.x, y.x); yt.y = fmaf(hs, k.y, y.y);
            yt.z = fmaf(hs, k.z, y.z); yt.w = fmaf(hs, k.w, y.w);
            *(float4*)&s.YT[oo] = yt;
        } else {
            float4 y = *(const float4*)&s.Y[oo];
            float4 a = *(const float4*)&s.ACC[oo];
            a.x += k.x; a.y += k.y; a.z += k.z; a.w += k.w;
            y.x = fmaf(h6, a.x, y.x); y.y = fmaf(h6, a.y, y.y);
            y.z = fmaf(h6, a.z, y.z); y.w = fmaf(h6, a.w, y.w);
            *(float4*)&s.Y[oo] = y;
        }
    }
}

// ---------------- one f-eval: SRC -> F0,F1 ----------------
__device__ __forceinline__ void feval(SMEM& s, const float* __restrict__ SRC, int tid) {
    gemm1_tanh(s, SRC, tid);
    __syncthreads();
    gemm2(s, tid);
    __syncthreads();
}

// ---------------- projection: out[sp] = Y @ Wfc + bfc ----------------
__device__ __forceinline__ void project(SMEM& s, float* __restrict__ out,
                                        int sp, int base, int B, int tid) {
    const int r  = tid >> 3;           // 0..31
    const int og = (tid & 7) * 4;      // 0..28
    float4 acc = *(const float4*)&s.bfc[og];
#pragma unroll 4
    for (int d = 0; d < Dd; d++) {
        float y = s.Y[r * SSTR + d];
        float4 w = *(const float4*)&s.Wfc[d * Oo + og];
        acc.x = fmaf(y, w.x, acc.x); acc.y = fmaf(y, w.y, acc.y);
        acc.z = fmaf(y, w.z, acc.z); acc.w = fmaf(y, w.w, acc.w);
    }
    size_t off = ((size_t)sp * B + base + r) * Oo + og;
    *(float4*)&out[off] = acc;
}

__global__ void __launch_bounds__(NT, 1)
node_kernel(const float* __restrict__ y0, const float* __restrict__ tarr,
            const float* __restrict__ W1, const float* __restrict__ b1,
            const float* __restrict__ W2, const float* __restrict__ b2,
            const float* __restrict__ Wfc, const float* __restrict__ bfc,
            float* __restrict__ out, int B, int T) {
    extern __shared__ float smem_f[];
    SMEM& s = *reinterpret_cast<SMEM*>(smem_f);
    const int tid  = threadIdx.x;
    const int base = blockIdx.x * RT;

    // ---- load weights / biases / t / y0 tile into SMEM ----
    for (int i = tid; i < Dd * Hh / 4; i += NT)
        ((float4*)s.W1)[i] = ((const float4*)W1)[i];
    for (int i = tid; i < Hh * Dd / 4; i += NT)
        ((float4*)s.W2)[i] = ((const float4*)W2)[i];
    for (int i = tid; i < Dd * Oo / 4; i += NT)
        ((float4*)s.Wfc)[i] = ((const float4*)Wfc)[i];
    for (int i = tid; i < Hh / 4; i += NT)
        ((float4*)s.b1)[i] = ((const float4*)b1)[i];
    if (tid < Dd / 4) ((float4*)s.b2)[tid] = ((const float4*)b2)[tid];
    if (tid < Oo / 4) ((float4*)s.bfc)[tid] = ((const float4*)bfc)[tid];
    if (tid < T && tid < 64) s.tv[tid] = tarr[tid];
    for (int i = tid; i < RT * Dd / 4; i += NT) {
        int r = i >> 4, d4 = i & 15;
        ((float4*)&s.Y[r * SSTR])[d4] = ((const float4*)&y0[(size_t)(base + r) * Dd])[d4];
    }
    __syncthreads();

    // ---- time integration ----
    for (int sp = 0; sp < T; sp++) {
        project(s, out, sp, base, B, tid);
        if (sp == T - 1) break;
        float dt = s.tv[sp + 1] - s.tv[sp];
        float h  = dt * 0.125f;    // dt / N_SUB

        for (int sub = 0; sub < 8; sub++) {
            feval(s, s.Y, tid);
            rk_update<0>(s, tid, h);
            __syncthreads();
            feval(s, s.YT, tid);
            rk_update<1>(s, tid, h);
            __syncthreads();
            feval(s, s.YT, tid);
            rk_update<2>(s, tid, h);
            __syncthreads();
            feval(s, s.YT, tid);
            rk_update<3>(s, tid, h);
            __syncthreads();
        }
    }
}

extern "C" void kernel_launch(void* const* d_in, const int* in_sizes, int n_in,
                              void* d_out, int out_size) {
    const float* y0  = (const float*)d_in[0];
    const float* t   = (const float*)d_in[1];
    const float* W1  = (const float*)d_in[2];
    const float* b1  = (const float*)d_in[3];
    const float* W2  = (const float*)d_in[4];
    const float* b2  = (const float*)d_in[5];
    const float* Wfc = (const float*)d_in[6];
    const float* bfc = (const float*)d_in[7];
    float* out = (float*)d_out;

    int B = in_sizes[0] / Dd;
    int T = in_sizes[1];

    size_t smem = sizeof(SMEM);
    cudaFuncSetAttribute(node_kernel, cudaFuncAttributeMaxDynamicSharedMemorySize, (int)smem);
    node_kernel<<<B / RT, NT, smem>>>(y0, t, W1, b1, W2, b2, Wfc, bfc, out, B, T);
}